// round 2
// baseline (speedup 1.0000x reference)
#include <cuda_runtime.h>
#include <math.h>

#define N_NODES 100000
#define N_EDGES 1600000
#define IN_FEATS 256
#define HIDDEN 128
#define NEG_SLOPE 0.2f

// ---------------- scratch (device globals; allocation-free) ----------------
__device__ float g_h[(size_t)N_NODES * HIDDEN];    // fc output of current layer
__device__ float g_x2[(size_t)N_NODES * HIDDEN];   // elu(layer1 out) = layer2 input
__device__ float g_el[N_NODES];
__device__ float g_er[N_NODES];
__device__ int   g_deg[N_NODES];
__device__ int   g_inc[N_NODES];
__device__ int   g_bsum[128];
__device__ int   g_off[N_NODES + 1];
__device__ int   g_cur[N_NODES];
__device__ int   g_esrc[N_EDGES];

// ---------------- CSR build ----------------
__global__ void k_zero_deg() {
    int i = blockIdx.x * blockDim.x + threadIdx.x;
    if (i < N_NODES) g_deg[i] = 0;
}

__global__ void k_count(const int* __restrict__ dst) {
    int i = blockIdx.x * blockDim.x + threadIdx.x;
    if (i < N_EDGES) atomicAdd(&g_deg[dst[i]], 1);
}

__global__ void k_scan1() {
    __shared__ int sm[1024];
    int i = blockIdx.x * 1024 + threadIdx.x;
    int v = (i < N_NODES) ? g_deg[i] : 0;
    sm[threadIdx.x] = v;
    __syncthreads();
    #pragma unroll
    for (int o = 1; o < 1024; o <<= 1) {
        int u = (threadIdx.x >= o) ? sm[threadIdx.x - o] : 0;
        __syncthreads();
        sm[threadIdx.x] += u;
        __syncthreads();
    }
    if (i < N_NODES) g_inc[i] = sm[threadIdx.x];
    if (threadIdx.x == 1023) g_bsum[blockIdx.x] = sm[1023];
}

__global__ void k_scan2(int nb) {
    __shared__ int sm[128];
    int t = threadIdx.x;
    int v = (t < nb) ? g_bsum[t] : 0;
    sm[t] = v;
    __syncthreads();
    #pragma unroll
    for (int o = 1; o < 128; o <<= 1) {
        int u = (t >= o) ? sm[t - o] : 0;
        __syncthreads();
        sm[t] += u;
        __syncthreads();
    }
    if (t < nb) g_bsum[t] = sm[t] - v;  // exclusive
}

__global__ void k_scan3() {
    int i = blockIdx.x * blockDim.x + threadIdx.x;
    if (i < N_NODES) {
        int off = g_inc[i] - g_deg[i] + g_bsum[i >> 10];
        g_off[i] = off;
        g_cur[i] = off;
    }
    if (i == 0) g_off[N_NODES] = N_EDGES;
}

__global__ void k_scatter(const int* __restrict__ src, const int* __restrict__ dst) {
    int i = blockIdx.x * blockDim.x + threadIdx.x;
    if (i < N_EDGES) {
        int p = atomicAdd(&g_cur[dst[i]], 1);
        g_esrc[p] = src[i];
    }
}

// ---------------- SGEMM: C[M,128] = A[M,K] @ W[128,K]^T ----------------
// 128x128 tile, 256 threads, 8x8 microtile, BK=8
__global__ __launch_bounds__(256) void k_sgemm(
    const float* __restrict__ A, const float* __restrict__ W,
    float* __restrict__ C, int M, int K)
{
    __shared__ float As[8][128];
    __shared__ float Bs[8][128];
    int tid = threadIdx.x;
    int row0 = blockIdx.x * 128;
    int tx = tid & 15, ty = tid >> 4;

    float acc[8][8];
    #pragma unroll
    for (int i = 0; i < 8; i++)
        #pragma unroll
        for (int j = 0; j < 8; j++) acc[i][j] = 0.f;

    int lr = tid >> 1;
    int lk = (tid & 1) * 4;

    for (int k0 = 0; k0 < K; k0 += 8) {
        float4 av = make_float4(0.f, 0.f, 0.f, 0.f);
        int gr = row0 + lr;
        if (gr < M) av = *(const float4*)(A + (size_t)gr * K + k0 + lk);
        As[lk + 0][lr] = av.x; As[lk + 1][lr] = av.y;
        As[lk + 2][lr] = av.z; As[lk + 3][lr] = av.w;
        float4 wv = *(const float4*)(W + (size_t)lr * K + k0 + lk);
        Bs[lk + 0][lr] = wv.x; Bs[lk + 1][lr] = wv.y;
        Bs[lk + 2][lr] = wv.z; Bs[lk + 3][lr] = wv.w;
        __syncthreads();
        #pragma unroll
        for (int k = 0; k < 8; k++) {
            float a[8], b[8];
            *(float4*)&a[0] = *(const float4*)&As[k][ty * 4];
            *(float4*)&a[4] = *(const float4*)&As[k][64 + ty * 4];
            *(float4*)&b[0] = *(const float4*)&Bs[k][tx * 4];
            *(float4*)&b[4] = *(const float4*)&Bs[k][64 + tx * 4];
            #pragma unroll
            for (int i = 0; i < 8; i++)
                #pragma unroll
                for (int j = 0; j < 8; j++)
                    acc[i][j] += a[i] * b[j];
        }
        __syncthreads();
    }

    #pragma unroll
    for (int i = 0; i < 8; i++) {
        int r = row0 + ((i < 4) ? (ty * 4 + i) : (64 + ty * 4 + (i - 4)));
        if (r < M) {
            *(float4*)(C + (size_t)r * 128 + tx * 4) =
                make_float4(acc[i][0], acc[i][1], acc[i][2], acc[i][3]);
            *(float4*)(C + (size_t)r * 128 + 64 + tx * 4) =
                make_float4(acc[i][4], acc[i][5], acc[i][6], acc[i][7]);
        }
    }
}

// ---------------- el/er: per-node dot(h, attn) ----------------
__global__ void k_elr(const float4* __restrict__ h4,
                      const float* __restrict__ al, const float* __restrict__ ar)
{
    int warp = (blockIdx.x * blockDim.x + threadIdx.x) >> 5;
    int lane = threadIdx.x & 31;
    if (warp >= N_NODES) return;
    float4 hv  = h4[(size_t)warp * 32 + lane];
    float4 alv = ((const float4*)al)[lane];
    float4 arv = ((const float4*)ar)[lane];
    float pl = hv.x * alv.x + hv.y * alv.y + hv.z * alv.z + hv.w * alv.w;
    float pr = hv.x * arv.x + hv.y * arv.y + hv.z * arv.z + hv.w * arv.w;
    #pragma unroll
    for (int o = 16; o; o >>= 1) {
        pl += __shfl_xor_sync(0xffffffffu, pl, o);
        pr += __shfl_xor_sync(0xffffffffu, pr, o);
    }
    if (lane == 0) { g_el[warp] = pl; g_er[warp] = pr; }
}

// ---------------- fused segment-softmax + aggregation, one warp per node --------
__global__ void k_agg(const float4* __restrict__ h4,
                      const float* __restrict__ bias,
                      float4* __restrict__ out4, int do_elu)
{
    int warp = (blockIdx.x * blockDim.x + threadIdx.x) >> 5;
    int lane = threadIdx.x & 31;
    if (warp >= N_NODES) return;
    int d = warp;
    int s = g_off[d], e = g_off[d + 1];
    float4 bv = ((const float4*)bias)[lane];
    float4 v;

    if (s == e) {
        v = bv;   // segment_sum over empty set = 0, plus bias
    } else {
        float er_d = g_er[d];
        // pass 1: segment max of leaky_relu scores
        float m = -INFINITY;
        for (int i = s + lane; i < e; i += 32) {
            float x = g_el[g_esrc[i]] + er_d;
            float sc = (x > 0.f) ? x : NEG_SLOPE * x;
            m = fmaxf(m, sc);
        }
        #pragma unroll
        for (int o = 16; o; o >>= 1) m = fmaxf(m, __shfl_xor_sync(0xffffffffu, m, o));

        // pass 2: online weighted sum (whole warp handles one edge at a time)
        float4 acc = make_float4(0.f, 0.f, 0.f, 0.f);
        float sumw = 0.f;
        for (int i = s; i < e; i++) {
            int sn = g_esrc[i];
            float x = g_el[sn] + er_d;
            float sc = (x > 0.f) ? x : NEG_SLOPE * x;
            float w = __expf(sc - m);
            sumw += w;
            float4 hv = h4[(size_t)sn * 32 + lane];
            acc.x += w * hv.x; acc.y += w * hv.y;
            acc.z += w * hv.z; acc.w += w * hv.w;
        }
        float inv = 1.f / sumw;
        v = make_float4(acc.x * inv + bv.x, acc.y * inv + bv.y,
                        acc.z * inv + bv.z, acc.w * inv + bv.w);
    }

    if (do_elu) {
        v.x = (v.x > 0.f) ? v.x : (__expf(v.x) - 1.f);
        v.y = (v.y > 0.f) ? v.y : (__expf(v.y) - 1.f);
        v.z = (v.z > 0.f) ? v.z : (__expf(v.z) - 1.f);
        v.w = (v.w > 0.f) ? v.w : (__expf(v.w) - 1.f);
    }
    out4[(size_t)d * 32 + lane] = v;
}

// ---------------- launch ----------------
extern "C" void kernel_launch(void* const* d_in, const int* in_sizes, int n_in,
                              void* d_out, int out_size)
{
    const float* feats = (const float*)d_in[0];
    const int*   src   = (const int*)d_in[1];
    const int*   dst   = (const int*)d_in[2];
    const float* W1    = (const float*)d_in[3];
    const float* al1   = (const float*)d_in[4];
    const float* ar1   = (const float*)d_in[5];
    const float* b1    = (const float*)d_in[6];
    const float* W2    = (const float*)d_in[7];
    const float* al2   = (const float*)d_in[8];
    const float* ar2   = (const float*)d_in[9];
    const float* b2    = (const float*)d_in[10];
    float* out = (float*)d_out;

    float *h, *x2;
    cudaGetSymbolAddress((void**)&h, g_h);
    cudaGetSymbolAddress((void**)&x2, g_x2);

    const int nodeGrid = (N_NODES + 255) / 256;
    const int edgeGrid = (N_EDGES + 255) / 256;
    const int scanBlocks = (N_NODES + 1023) / 1024;
    const int warpGrid = (N_NODES * 32 + 127) / 128;   // 1 warp per node, 128-thread blocks
    const int gemmGrid = (N_NODES + 127) / 128;

    // CSR by dst (rebuilt every call; graph-capture safe, no allocations)
    k_zero_deg<<<nodeGrid, 256>>>();
    k_count<<<edgeGrid, 256>>>(dst);
    k_scan1<<<scanBlocks, 1024>>>();
    k_scan2<<<1, 128>>>(scanBlocks);
    k_scan3<<<nodeGrid, 256>>>();
    k_scatter<<<edgeGrid, 256>>>(src, dst);

    // ---- layer 1 ----
    k_sgemm<<<gemmGrid, 256>>>(feats, W1, h, N_NODES, IN_FEATS);
    k_elr<<<warpGrid, 128>>>((const float4*)h, al1, ar1);
    k_agg<<<warpGrid, 128>>>((const float4*)h, b1, (float4*)x2, 1);

    // ---- layer 2 ----
    k_sgemm<<<gemmGrid, 256>>>(x2, W2, h, N_NODES, HIDDEN);
    k_elr<<<warpGrid, 128>>>((const float4*)h, al2, ar2);
    k_agg<<<warpGrid, 128>>>((const float4*)h, b2, (float4*)out, 0);
}

// round 3
// speedup vs baseline: 1.2656x; 1.2656x over previous
#include <cuda_runtime.h>
#include <cuda_bf16.h>
#include <math.h>

#define N_NODES 100000
#define N_EDGES 1600000
#define IN_FEATS 256
#define HIDDEN 128
#define NEG_SLOPE 0.2f

// ---------------- scratch (device globals; allocation-free) ----------------
__device__ float g_h[(size_t)N_NODES * HIDDEN];    // fc output of current layer
__device__ float g_x2[(size_t)N_NODES * HIDDEN];   // elu(layer1 out) = layer2 input
__device__ float g_el[N_NODES];
__device__ float g_er[N_NODES];
__device__ int   g_deg[N_NODES];
__device__ int   g_inc[N_NODES];
__device__ int   g_bsum[128];
__device__ int   g_off[N_NODES + 1];
__device__ int   g_cur[N_NODES];
__device__ int   g_esrc[N_EDGES];

// ---------------- CSR build ----------------
__global__ void k_zero_deg() {
    int i = blockIdx.x * blockDim.x + threadIdx.x;
    if (i < N_NODES) g_deg[i] = 0;
}

__global__ void k_count(const int* __restrict__ dst) {
    int i = blockIdx.x * blockDim.x + threadIdx.x;
    if (i < N_EDGES) atomicAdd(&g_deg[dst[i]], 1);
}

__global__ void k_scan1() {
    __shared__ int sm[1024];
    int i = blockIdx.x * 1024 + threadIdx.x;
    int v = (i < N_NODES) ? g_deg[i] : 0;
    sm[threadIdx.x] = v;
    __syncthreads();
    #pragma unroll
    for (int o = 1; o < 1024; o <<= 1) {
        int u = (threadIdx.x >= o) ? sm[threadIdx.x - o] : 0;
        __syncthreads();
        sm[threadIdx.x] += u;
        __syncthreads();
    }
    if (i < N_NODES) g_inc[i] = sm[threadIdx.x];
    if (threadIdx.x == 1023) g_bsum[blockIdx.x] = sm[1023];
}

__global__ void k_scan2(int nb) {
    __shared__ int sm[128];
    int t = threadIdx.x;
    int v = (t < nb) ? g_bsum[t] : 0;
    sm[t] = v;
    __syncthreads();
    #pragma unroll
    for (int o = 1; o < 128; o <<= 1) {
        int u = (t >= o) ? sm[t - o] : 0;
        __syncthreads();
        sm[t] += u;
        __syncthreads();
    }
    if (t < nb) g_bsum[t] = sm[t] - v;  // exclusive
}

__global__ void k_scan3() {
    int i = blockIdx.x * blockDim.x + threadIdx.x;
    if (i < N_NODES) {
        int off = g_inc[i] - g_deg[i] + g_bsum[i >> 10];
        g_off[i] = off;
        g_cur[i] = off;
    }
    if (i == 0) g_off[N_NODES] = N_EDGES;
}

__global__ void k_scatter(const int* __restrict__ src, const int* __restrict__ dst) {
    int i = blockIdx.x * blockDim.x + threadIdx.x;
    if (i < N_EDGES) {
        int p = atomicAdd(&g_cur[dst[i]], 1);
        g_esrc[p] = src[i];
    }
}

// ---------------- bf16x3 tensor-core GEMM: C[M,128] = A[M,K] @ W[128,K]^T ---
// 128x128 tile, 256 threads (8 warps, each 64x32), BK=32, register prefetch.
// Split each fp32 into bf16 hi + bf16 lo; D += Ahi*Bhi + Ahi*Blo + Alo*Bhi.
// Residual error ~2^-16 relative — effectively fp32 for the 1e-3 threshold.

#define SSTR 18   // uint32 (bf16x2-pair) stride per row: 16 pairs + 2 pad

__device__ __forceinline__ void mma16816(float* d, const unsigned* a, const unsigned* b) {
    asm volatile(
        "mma.sync.aligned.m16n8k16.row.col.f32.bf16.bf16.f32 "
        "{%0,%1,%2,%3}, {%4,%5,%6,%7}, {%8,%9}, {%0,%1,%2,%3};\n"
        : "+f"(d[0]), "+f"(d[1]), "+f"(d[2]), "+f"(d[3])
        : "r"(a[0]), "r"(a[1]), "r"(a[2]), "r"(a[3]), "r"(b[0]), "r"(b[1]));
}

__device__ __forceinline__ unsigned pack_hi(float a, float b, float& la, float& lb) {
    __nv_bfloat16 ha = __float2bfloat16_rn(a);
    __nv_bfloat16 hb = __float2bfloat16_rn(b);
    la = a - __bfloat162float(ha);
    lb = b - __bfloat162float(hb);
    return ((unsigned)__bfloat16_as_ushort(hb) << 16) | (unsigned)__bfloat16_as_ushort(ha);
}

__device__ __forceinline__ unsigned pack_lo(float la, float lb) {
    return ((unsigned)__bfloat16_as_ushort(__float2bfloat16_rn(lb)) << 16) |
           (unsigned)__bfloat16_as_ushort(__float2bfloat16_rn(la));
}

__global__ __launch_bounds__(256) void k_gemm_bf16x3(
    const float* __restrict__ A, const float* __restrict__ W,
    float* __restrict__ C, int M, int K)
{
    __shared__ unsigned sAhi[128 * SSTR];
    __shared__ unsigned sAlo[128 * SSTR];
    __shared__ unsigned sBhi[128 * SSTR];
    __shared__ unsigned sBlo[128 * SSTR];

    const int tid  = threadIdx.x;
    const int lane = tid & 31, wid = tid >> 5;
    const int g = lane >> 2, t = lane & 3;
    const int wm = wid >> 2, wn = wid & 3;           // 2 x 4 warp grid
    const int row0 = blockIdx.x * 128;

    float acc[4][4][4];
    #pragma unroll
    for (int mt = 0; mt < 4; mt++)
        #pragma unroll
        for (int nt = 0; nt < 4; nt++)
            #pragma unroll
            for (int j = 0; j < 4; j++) acc[mt][nt][j] = 0.f;

    int lrow[4], lq[4];
    #pragma unroll
    for (int i = 0; i < 4; i++) { int idx = tid + i * 256; lrow[i] = idx >> 3; lq[i] = idx & 7; }

    float4 ra[4], rb[4];
    const int NC = K / 32;

    // prologue: load chunk 0 to registers
    #pragma unroll
    for (int i = 0; i < 4; i++) {
        int gr = row0 + lrow[i];
        ra[i] = (gr < M) ? *(const float4*)(A + (size_t)gr * K + lq[i] * 4)
                         : make_float4(0.f, 0.f, 0.f, 0.f);
        rb[i] = *(const float4*)(W + (size_t)lrow[i] * K + lq[i] * 4);
    }

    for (int c = 0; c < NC; c++) {
        // regs -> smem (split into bf16 hi/lo)
        #pragma unroll
        for (int i = 0; i < 4; i++) {
            int base = lrow[i] * SSTR + lq[i] * 2;
            float l0, l1, l2, l3;
            unsigned h0 = pack_hi(ra[i].x, ra[i].y, l0, l1);
            unsigned h1 = pack_hi(ra[i].z, ra[i].w, l2, l3);
            sAhi[base] = h0; sAhi[base + 1] = h1;
            sAlo[base] = pack_lo(l0, l1); sAlo[base + 1] = pack_lo(l2, l3);
            h0 = pack_hi(rb[i].x, rb[i].y, l0, l1);
            h1 = pack_hi(rb[i].z, rb[i].w, l2, l3);
            sBhi[base] = h0; sBhi[base + 1] = h1;
            sBlo[base] = pack_lo(l0, l1); sBlo[base + 1] = pack_lo(l2, l3);
        }
        __syncthreads();

        // prefetch next chunk while MMAs run
        if (c + 1 < NC) {
            int k0 = (c + 1) * 32;
            #pragma unroll
            for (int i = 0; i < 4; i++) {
                int gr = row0 + lrow[i];
                ra[i] = (gr < M) ? *(const float4*)(A + (size_t)gr * K + k0 + lq[i] * 4)
                                 : make_float4(0.f, 0.f, 0.f, 0.f);
                rb[i] = *(const float4*)(W + (size_t)lrow[i] * K + k0 + lq[i] * 4);
            }
        }

        #pragma unroll
        for (int ks = 0; ks < 2; ks++) {
            const int pb = ks * 8;
            unsigned fahi[4][4], falo[4][4], fbhi[4][2], fblo[4][2];
            #pragma unroll
            for (int mt = 0; mt < 4; mt++) {
                int r0 = (wm * 64 + mt * 16 + g) * SSTR + pb + t;
                int r1 = r0 + 8 * SSTR;
                fahi[mt][0] = sAhi[r0];     fahi[mt][1] = sAhi[r1];
                fahi[mt][2] = sAhi[r0 + 4]; fahi[mt][3] = sAhi[r1 + 4];
                falo[mt][0] = sAlo[r0];     falo[mt][1] = sAlo[r1];
                falo[mt][2] = sAlo[r0 + 4]; falo[mt][3] = sAlo[r1 + 4];
            }
            #pragma unroll
            for (int nt = 0; nt < 4; nt++) {
                int rn = (wn * 32 + nt * 8 + g) * SSTR + pb + t;
                fbhi[nt][0] = sBhi[rn]; fbhi[nt][1] = sBhi[rn + 4];
                fblo[nt][0] = sBlo[rn]; fblo[nt][1] = sBlo[rn + 4];
            }
            #pragma unroll
            for (int mt = 0; mt < 4; mt++)
                #pragma unroll
                for (int nt = 0; nt < 4; nt++) {
                    mma16816(acc[mt][nt], fahi[mt], fbhi[nt]);
                    mma16816(acc[mt][nt], fahi[mt], fblo[nt]);
                    mma16816(acc[mt][nt], falo[mt], fbhi[nt]);
                }
        }
        __syncthreads();
    }

    // epilogue
    #pragma unroll
    for (int mt = 0; mt < 4; mt++)
        #pragma unroll
        for (int nt = 0; nt < 4; nt++) {
            int r = row0 + wm * 64 + mt * 16 + g;
            int col = wn * 32 + nt * 8 + t * 2;
            if (r < M)
                *(float2*)(C + (size_t)r * 128 + col) =
                    make_float2(acc[mt][nt][0], acc[mt][nt][1]);
            if (r + 8 < M)
                *(float2*)(C + (size_t)(r + 8) * 128 + col) =
                    make_float2(acc[mt][nt][2], acc[mt][nt][3]);
        }
}

// ---------------- el/er: per-node dot(h, attn) ----------------
__global__ void k_elr(const float4* __restrict__ h4,
                      const float* __restrict__ al, const float* __restrict__ ar)
{
    int warp = (blockIdx.x * blockDim.x + threadIdx.x) >> 5;
    int lane = threadIdx.x & 31;
    if (warp >= N_NODES) return;
    float4 hv  = h4[(size_t)warp * 32 + lane];
    float4 alv = ((const float4*)al)[lane];
    float4 arv = ((const float4*)ar)[lane];
    float pl = hv.x * alv.x + hv.y * alv.y + hv.z * alv.z + hv.w * alv.w;
    float pr = hv.x * arv.x + hv.y * arv.y + hv.z * arv.z + hv.w * arv.w;
    #pragma unroll
    for (int o = 16; o; o >>= 1) {
        pl += __shfl_xor_sync(0xffffffffu, pl, o);
        pr += __shfl_xor_sync(0xffffffffu, pr, o);
    }
    if (lane == 0) { g_el[warp] = pl; g_er[warp] = pr; }
}

// ---------------- fused segment-softmax + aggregation, one warp per node --------
__global__ void k_agg(const float4* __restrict__ h4,
                      const float* __restrict__ bias,
                      float4* __restrict__ out4, int do_elu)
{
    int warp = (blockIdx.x * blockDim.x + threadIdx.x) >> 5;
    int lane = threadIdx.x & 31;
    if (warp >= N_NODES) return;
    int d = warp;
    int s = g_off[d], e = g_off[d + 1];
    float4 bv = ((const float4*)bias)[lane];
    float4 v;

    if (s == e) {
        v = bv;   // segment_sum over empty set = 0, plus bias
    } else {
        float er_d = g_er[d];
        // pass 1: segment max of leaky_relu scores
        float m = -INFINITY;
        for (int i = s + lane; i < e; i += 32) {
            float x = g_el[g_esrc[i]] + er_d;
            float sc = (x > 0.f) ? x : NEG_SLOPE * x;
            m = fmaxf(m, sc);
        }
        #pragma unroll
        for (int o = 16; o; o >>= 1) m = fmaxf(m, __shfl_xor_sync(0xffffffffu, m, o));

        // pass 2: online weighted sum (whole warp handles one edge at a time)
        float4 acc = make_float4(0.f, 0.f, 0.f, 0.f);
        float sumw = 0.f;
        for (int i = s; i < e; i++) {
            int sn = g_esrc[i];
            float x = g_el[sn] + er_d;
            float sc = (x > 0.f) ? x : NEG_SLOPE * x;
            float w = __expf(sc - m);
            sumw += w;
            float4 hv = h4[(size_t)sn * 32 + lane];
            acc.x += w * hv.x; acc.y += w * hv.y;
            acc.z += w * hv.z; acc.w += w * hv.w;
        }
        float inv = 1.f / sumw;
        v = make_float4(acc.x * inv + bv.x, acc.y * inv + bv.y,
                        acc.z * inv + bv.z, acc.w * inv + bv.w);
    }

    if (do_elu) {
        v.x = (v.x > 0.f) ? v.x : (__expf(v.x) - 1.f);
        v.y = (v.y > 0.f) ? v.y : (__expf(v.y) - 1.f);
        v.z = (v.z > 0.f) ? v.z : (__expf(v.z) - 1.f);
        v.w = (v.w > 0.f) ? v.w : (__expf(v.w) - 1.f);
    }
    out4[(size_t)d * 32 + lane] = v;
}

// ---------------- launch ----------------
extern "C" void kernel_launch(void* const* d_in, const int* in_sizes, int n_in,
                              void* d_out, int out_size)
{
    const float* feats = (const float*)d_in[0];
    const int*   src   = (const int*)d_in[1];
    const int*   dst   = (const int*)d_in[2];
    const float* W1    = (const float*)d_in[3];
    const float* al1   = (const float*)d_in[4];
    const float* ar1   = (const float*)d_in[5];
    const float* b1    = (const float*)d_in[6];
    const float* W2    = (const float*)d_in[7];
    const float* al2   = (const float*)d_in[8];
    const float* ar2   = (const float*)d_in[9];
    const float* b2    = (const float*)d_in[10];
    float* out = (float*)d_out;

    float *h, *x2;
    cudaGetSymbolAddress((void**)&h, g_h);
    cudaGetSymbolAddress((void**)&x2, g_x2);

    const int nodeGrid = (N_NODES + 255) / 256;
    const int edgeGrid = (N_EDGES + 255) / 256;
    const int scanBlocks = (N_NODES + 1023) / 1024;
    const int warpGrid = (N_NODES * 32 + 127) / 128;   // 1 warp per node, 128-thread blocks
    const int gemmGrid = (N_NODES + 127) / 128;

    // CSR by dst (rebuilt every call; graph-capture safe, no allocations)
    k_zero_deg<<<nodeGrid, 256>>>();
    k_count<<<edgeGrid, 256>>>(dst);
    k_scan1<<<scanBlocks, 1024>>>();
    k_scan2<<<1, 128>>>(scanBlocks);
    k_scan3<<<nodeGrid, 256>>>();
    k_scatter<<<edgeGrid, 256>>>(src, dst);

    // ---- layer 1 ----
    k_gemm_bf16x3<<<gemmGrid, 256>>>(feats, W1, h, N_NODES, IN_FEATS);
    k_elr<<<warpGrid, 128>>>((const float4*)h, al1, ar1);
    k_agg<<<warpGrid, 128>>>((const float4*)h, b1, (float4*)x2, 1);

    // ---- layer 2 ----
    k_gemm_bf16x3<<<gemmGrid, 256>>>(x2, W2, h, N_NODES, HIDDEN);
    k_elr<<<warpGrid, 128>>>((const float4*)h, al2, ar2);
    k_agg<<<warpGrid, 128>>>((const float4*)h, b2, (float4*)out, 0);
}

// round 7
// speedup vs baseline: 1.3581x; 1.0731x over previous
#include <cuda_runtime.h>
#include <cuda_bf16.h>
#include <math.h>

#define N_NODES 100000
#define N_EDGES 1600000
#define IN_FEATS 256
#define HIDDEN 128
#define NEG_SLOPE 0.2f

// ---------------- scratch (device globals; allocation-free) ----------------
__device__ float g_h[(size_t)N_NODES * HIDDEN];    // fc output of current layer
__device__ float g_x2[(size_t)N_NODES * HIDDEN];   // elu(layer1 out) = layer2 input
__device__ float g_el[N_NODES];
__device__ float g_er[N_NODES];
__device__ int   g_deg[N_NODES];
__device__ int   g_inc[N_NODES];
__device__ int   g_bsum[128];
__device__ int   g_off[N_NODES + 1];
__device__ int   g_cur[N_NODES];
__device__ int   g_esrc[N_EDGES];
// pre-split weights: packed bf16x2 hi/lo planes
__device__ unsigned g_w1hi[128 * IN_FEATS / 2];
__device__ unsigned g_w1lo[128 * IN_FEATS / 2];
__device__ unsigned g_w2hi[128 * HIDDEN / 2];
__device__ unsigned g_w2lo[128 * HIDDEN / 2];

// ---------------- CSR build ----------------
__global__ void k_count(const int* __restrict__ dst) {
    int i = blockIdx.x * blockDim.x + threadIdx.x;
    if (i < N_EDGES) atomicAdd(&g_deg[dst[i]], 1);
}

__global__ void k_scan1() {
    __shared__ int sm[1024];
    int i = blockIdx.x * 1024 + threadIdx.x;
    int v = (i < N_NODES) ? g_deg[i] : 0;
    sm[threadIdx.x] = v;
    __syncthreads();
    #pragma unroll
    for (int o = 1; o < 1024; o <<= 1) {
        int u = (threadIdx.x >= o) ? sm[threadIdx.x - o] : 0;
        __syncthreads();
        sm[threadIdx.x] += u;
        __syncthreads();
    }
    if (i < N_NODES) g_inc[i] = sm[threadIdx.x];
    if (threadIdx.x == 1023) g_bsum[blockIdx.x] = sm[1023];
}

__global__ void k_scan2(int nb) {
    __shared__ int sm[128];
    int t = threadIdx.x;
    int v = (t < nb) ? g_bsum[t] : 0;
    sm[t] = v;
    __syncthreads();
    #pragma unroll
    for (int o = 1; o < 128; o <<= 1) {
        int u = (t >= o) ? sm[t - o] : 0;
        __syncthreads();
        sm[t] += u;
        __syncthreads();
    }
    if (t < nb) g_bsum[t] = sm[t] - v;  // exclusive
}

__global__ void k_scan3() {
    int i = blockIdx.x * blockDim.x + threadIdx.x;
    if (i < N_NODES) {
        int off = g_inc[i] - g_deg[i] + g_bsum[i >> 10];
        g_off[i] = off;
        g_cur[i] = off;
    }
    if (i == 0) g_off[N_NODES] = N_EDGES;
}

__global__ void k_scatter(const int* __restrict__ src, const int* __restrict__ dst) {
    int i = blockIdx.x * blockDim.x + threadIdx.x;
    if (i < N_EDGES) {
        int p = atomicAdd(&g_cur[dst[i]], 1);
        g_esrc[p] = src[i];
    }
}

// ---------------- fp32 -> bf16 hi/lo helpers ----------------
__device__ __forceinline__ unsigned pack_hi(float a, float b, float& la, float& lb) {
    __nv_bfloat16 ha = __float2bfloat16_rn(a);
    __nv_bfloat16 hb = __float2bfloat16_rn(b);
    la = a - __bfloat162float(ha);
    lb = b - __bfloat162float(hb);
    return ((unsigned)__bfloat16_as_ushort(hb) << 16) | (unsigned)__bfloat16_as_ushort(ha);
}

__device__ __forceinline__ unsigned pack_lo(float la, float lb) {
    return ((unsigned)__bfloat16_as_ushort(__float2bfloat16_rn(lb)) << 16) |
           (unsigned)__bfloat16_as_ushort(__float2bfloat16_rn(la));
}

// one-time weight split: W[128,K] fp32 -> hi/lo packed bf16x2 planes
__global__ void k_splitW(const float* __restrict__ W, unsigned* __restrict__ hi,
                         unsigned* __restrict__ lo, int npairs) {
    int i = blockIdx.x * blockDim.x + threadIdx.x;
    if (i < npairs) {
        float a = W[2 * i], b = W[2 * i + 1];
        float la, lb;
        unsigned h = pack_hi(a, b, la, lb);
        hi[i] = h;
        lo[i] = pack_lo(la, lb);
    }
}

// ---------------- bf16x3 tensor-core GEMM + fused el/er ----------------
// C[M,128] = A[M,K] @ W[128,K]^T ; also writes g_el/g_er = C-row dot al/ar.
// 128x128 tile, 256 threads (8 warps, each 64x32), BK=32, register prefetch.
// B (weights) arrive pre-split as packed bf16x2 hi/lo planes.

#define SSTR 18   // uint32 (bf16x2-pair) stride per row: 16 pairs + 2 pad

__device__ __forceinline__ void mma16816(float* d, const unsigned* a, const unsigned* b) {
    asm volatile(
        "mma.sync.aligned.m16n8k16.row.col.f32.bf16.bf16.f32 "
        "{%0,%1,%2,%3}, {%4,%5,%6,%7}, {%8,%9}, {%0,%1,%2,%3};\n"
        : "+f"(d[0]), "+f"(d[1]), "+f"(d[2]), "+f"(d[3])
        : "r"(a[0]), "r"(a[1]), "r"(a[2]), "r"(a[3]), "r"(b[0]), "r"(b[1]));
}

__global__ __launch_bounds__(256) void k_gemm_bf16x3(
    const float* __restrict__ A,
    const unsigned* __restrict__ Whi, const unsigned* __restrict__ Wlo,
    const float* __restrict__ al, const float* __restrict__ ar,
    float* __restrict__ C, int M, int K)
{
    __shared__ unsigned sAhi[128 * SSTR];
    __shared__ unsigned sAlo[128 * SSTR];
    __shared__ unsigned sBhi[128 * SSTR];
    __shared__ unsigned sBlo[128 * SSTR];
    __shared__ float sel[128], ser[128];

    const int tid  = threadIdx.x;
    const int lane = tid & 31, wid = tid >> 5;
    const int g = lane >> 2, t = lane & 3;
    const int wm = wid >> 2, wn = wid & 3;           // 2 x 4 warp grid
    const int row0 = blockIdx.x * 128;
    const int K2 = K >> 1;                            // pairs per W row

    if (tid < 128) { sel[tid] = 0.f; ser[tid] = 0.f; }

    float acc[4][4][4];
    #pragma unroll
    for (int mt = 0; mt < 4; mt++)
        #pragma unroll
        for (int nt = 0; nt < 4; nt++)
            #pragma unroll
            for (int j = 0; j < 4; j++) acc[mt][nt][j] = 0.f;

    int lrow[4], lq[4];
    #pragma unroll
    for (int i = 0; i < 4; i++) { int idx = tid + i * 256; lrow[i] = idx >> 3; lq[i] = idx & 7; }

    float4 ra[4];
    uint2 bh[4], bl[4];
    const int NC = K / 32;

    // prologue: load chunk 0 to registers
    #pragma unroll
    for (int i = 0; i < 4; i++) {
        int gr = row0 + lrow[i];
        ra[i] = (gr < M) ? *(const float4*)(A + (size_t)gr * K + lq[i] * 4)
                         : make_float4(0.f, 0.f, 0.f, 0.f);
        int bidx = lrow[i] * K2 + lq[i] * 2;
        bh[i] = *(const uint2*)(Whi + bidx);
        bl[i] = *(const uint2*)(Wlo + bidx);
    }

    for (int c = 0; c < NC; c++) {
        // regs -> smem (A split into bf16 hi/lo; B pre-split)
        #pragma unroll
        for (int i = 0; i < 4; i++) {
            int base = lrow[i] * SSTR + lq[i] * 2;
            float l0, l1, l2, l3;
            unsigned h0 = pack_hi(ra[i].x, ra[i].y, l0, l1);
            unsigned h1 = pack_hi(ra[i].z, ra[i].w, l2, l3);
            sAhi[base] = h0; sAhi[base + 1] = h1;
            sAlo[base] = pack_lo(l0, l1); sAlo[base + 1] = pack_lo(l2, l3);
            sBhi[base] = bh[i].x; sBhi[base + 1] = bh[i].y;
            sBlo[base] = bl[i].x; sBlo[base + 1] = bl[i].y;
        }
        __syncthreads();

        // prefetch next chunk while MMAs run
        if (c + 1 < NC) {
            int k0 = (c + 1) * 32;
            #pragma unroll
            for (int i = 0; i < 4; i++) {
                int gr = row0 + lrow[i];
                ra[i] = (gr < M) ? *(const float4*)(A + (size_t)gr * K + k0 + lq[i] * 4)
                                 : make_float4(0.f, 0.f, 0.f, 0.f);
                int bidx = lrow[i] * K2 + (k0 >> 1) + lq[i] * 2;
                bh[i] = *(const uint2*)(Whi + bidx);
                bl[i] = *(const uint2*)(Wlo + bidx);
            }
        }

        #pragma unroll
        for (int ks = 0; ks < 2; ks++) {
            const int pb = ks * 8;
            unsigned fahi[4][4], falo[4][4], fbhi[4][2], fblo[4][2];
            #pragma unroll
            for (int mt = 0; mt < 4; mt++) {
                int r0 = (wm * 64 + mt * 16 + g) * SSTR + pb + t;
                int r1 = r0 + 8 * SSTR;
                fahi[mt][0] = sAhi[r0];     fahi[mt][1] = sAhi[r1];
                fahi[mt][2] = sAhi[r0 + 4]; fahi[mt][3] = sAhi[r1 + 4];
                falo[mt][0] = sAlo[r0];     falo[mt][1] = sAlo[r1];
                falo[mt][2] = sAlo[r0 + 4]; falo[mt][3] = sAlo[r1 + 4];
            }
            #pragma unroll
            for (int nt = 0; nt < 4; nt++) {
                int rn = (wn * 32 + nt * 8 + g) * SSTR + pb + t;
                fbhi[nt][0] = sBhi[rn]; fbhi[nt][1] = sBhi[rn + 4];
                fblo[nt][0] = sBlo[rn]; fblo[nt][1] = sBlo[rn + 4];
            }
            #pragma unroll
            for (int mt = 0; mt < 4; mt++)
                #pragma unroll
                for (int nt = 0; nt < 4; nt++) {
                    mma16816(acc[mt][nt], fahi[mt], fbhi[nt]);
                    mma16816(acc[mt][nt], fahi[mt], fblo[nt]);
                    mma16816(acc[mt][nt], falo[mt], fbhi[nt]);
                }
        }
        __syncthreads();
    }

    // epilogue: store C, and fused el/er row dots
    float alv[8], arv[8];
    #pragma unroll
    for (int nt = 0; nt < 4; nt++) {
        int cix = wn * 32 + nt * 8 + t * 2;
        alv[2 * nt] = al[cix];     alv[2 * nt + 1] = al[cix + 1];
        arv[2 * nt] = ar[cix];     arv[2 * nt + 1] = ar[cix + 1];
    }

    #pragma unroll
    for (int mt = 0; mt < 4; mt++) {
        float eA = 0.f, rA = 0.f, eB = 0.f, rB = 0.f;
        #pragma unroll
        for (int nt = 0; nt < 4; nt++) {
            int r = row0 + wm * 64 + mt * 16 + g;
            int col = wn * 32 + nt * 8 + t * 2;
            if (r < M)
                *(float2*)(C + (size_t)r * 128 + col) =
                    make_float2(acc[mt][nt][0], acc[mt][nt][1]);
            if (r + 8 < M)
                *(float2*)(C + (size_t)(r + 8) * 128 + col) =
                    make_float2(acc[mt][nt][2], acc[mt][nt][3]);
            eA += acc[mt][nt][0] * alv[2 * nt] + acc[mt][nt][1] * alv[2 * nt + 1];
            rA += acc[mt][nt][0] * arv[2 * nt] + acc[mt][nt][1] * arv[2 * nt + 1];
            eB += acc[mt][nt][2] * alv[2 * nt] + acc[mt][nt][3] * alv[2 * nt + 1];
            rB += acc[mt][nt][2] * arv[2 * nt] + acc[mt][nt][3] * arv[2 * nt + 1];
        }
        // reduce over the quad (t = lane bits 0..1)
        #pragma unroll
        for (int o = 1; o <= 2; o <<= 1) {
            eA += __shfl_xor_sync(0xffffffffu, eA, o);
            rA += __shfl_xor_sync(0xffffffffu, rA, o);
            eB += __shfl_xor_sync(0xffffffffu, eB, o);
            rB += __shfl_xor_sync(0xffffffffu, rB, o);
        }
        if (t == 0) {
            int lr0 = wm * 64 + mt * 16 + g;
            atomicAdd(&sel[lr0], eA);     atomicAdd(&ser[lr0], rA);
            atomicAdd(&sel[lr0 + 8], eB); atomicAdd(&ser[lr0 + 8], rB);
        }
    }
    __syncthreads();
    if (tid < 128 && row0 + tid < M) {
        g_el[row0 + tid] = sel[tid];
        g_er[row0 + tid] = ser[tid];
    }
}

// ---------------- fused segment-softmax + aggregation, one warp per node --------
__global__ void k_agg(const float4* __restrict__ h4,
                      const float* __restrict__ bias,
                      float4* __restrict__ out4, int do_elu)
{
    int warp = (blockIdx.x * blockDim.x + threadIdx.x) >> 5;
    int lane = threadIdx.x & 31;
    if (warp >= N_NODES) return;
    int d = warp;
    int s = g_off[d], e = g_off[d + 1];
    float4 bv = ((const float4*)bias)[lane];
    float4 v;

    if (s == e) {
        v = bv;   // segment_sum over empty set = 0, plus bias
    } else {
        float er_d = g_er[d];
        // pass 1: segment max of leaky_relu scores
        float m = -INFINITY;
        for (int i = s + lane; i < e; i += 32) {
            float x = g_el[g_esrc[i]] + er_d;
            float sc = (x > 0.f) ? x : NEG_SLOPE * x;
            m = fmaxf(m, sc);
        }
        #pragma unroll
        for (int o = 16; o; o >>= 1) m = fmaxf(m, __shfl_xor_sync(0xffffffffu, m, o));

        // pass 2: online weighted sum, 2 edges per iteration for MLP
        float4 acc = make_float4(0.f, 0.f, 0.f, 0.f);
        float sumw = 0.f;
        int i = s;
        for (; i + 1 < e; i += 2) {
            int sn0 = g_esrc[i], sn1 = g_esrc[i + 1];
            float4 hv0 = h4[(size_t)sn0 * 32 + lane];
            float4 hv1 = h4[(size_t)sn1 * 32 + lane];
            float x0 = g_el[sn0] + er_d;
            float x1 = g_el[sn1] + er_d;
            float sc0 = (x0 > 0.f) ? x0 : NEG_SLOPE * x0;
            float sc1 = (x1 > 0.f) ? x1 : NEG_SLOPE * x1;
            float w0 = __expf(sc0 - m);
            float w1 = __expf(sc1 - m);
            sumw += w0 + w1;
            acc.x += w0 * hv0.x + w1 * hv1.x;
            acc.y += w0 * hv0.y + w1 * hv1.y;
            acc.z += w0 * hv0.z + w1 * hv1.z;
            acc.w += w0 * hv0.w + w1 * hv1.w;
        }
        if (i < e) {
            int sn = g_esrc[i];
            float x = g_el[sn] + er_d;
            float sc = (x > 0.f) ? x : NEG_SLOPE * x;
            float w = __expf(sc - m);
            sumw += w;
            float4 hv = h4[(size_t)sn * 32 + lane];
            acc.x += w * hv.x; acc.y += w * hv.y;
            acc.z += w * hv.z; acc.w += w * hv.w;
        }
        float inv = 1.f / sumw;
        v = make_float4(acc.x * inv + bv.x, acc.y * inv + bv.y,
                        acc.z * inv + bv.z, acc.w * inv + bv.w);
    }

    if (do_elu) {
        v.x = (v.x > 0.f) ? v.x : (__expf(v.x) - 1.f);
        v.y = (v.y > 0.f) ? v.y : (__expf(v.y) - 1.f);
        v.z = (v.z > 0.f) ? v.z : (__expf(v.z) - 1.f);
        v.w = (v.w > 0.f) ? v.w : (__expf(v.w) - 1.f);
    }
    out4[(size_t)d * 32 + lane] = v;
}

// ---------------- launch ----------------
extern "C" void kernel_launch(void* const* d_in, const int* in_sizes, int n_in,
                              void* d_out, int out_size)
{
    const float* feats = (const float*)d_in[0];
    const int*   src   = (const int*)d_in[1];
    const int*   dst   = (const int*)d_in[2];
    const float* W1    = (const float*)d_in[3];
    const float* al1   = (const float*)d_in[4];
    const float* ar1   = (const float*)d_in[5];
    const float* b1    = (const float*)d_in[6];
    const float* W2    = (const float*)d_in[7];
    const float* al2   = (const float*)d_in[8];
    const float* ar2   = (const float*)d_in[9];
    const float* b2    = (const float*)d_in[10];
    float* out = (float*)d_out;

    float *h, *x2;
    unsigned *w1hi, *w1lo, *w2hi, *w2lo;
    int *degp;
    cudaGetSymbolAddress((void**)&h, g_h);
    cudaGetSymbolAddress((void**)&x2, g_x2);
    cudaGetSymbolAddress((void**)&w1hi, g_w1hi);
    cudaGetSymbolAddress((void**)&w1lo, g_w1lo);
    cudaGetSymbolAddress((void**)&w2hi, g_w2hi);
    cudaGetSymbolAddress((void**)&w2lo, g_w2lo);
    cudaGetSymbolAddress((void**)&degp, g_deg);

    const int nodeGrid = (N_NODES + 255) / 256;
    const int edgeGrid = (N_EDGES + 255) / 256;
    const int scanBlocks = (N_NODES + 1023) / 1024;
    const int warpGrid = (N_NODES * 32 + 127) / 128;   // 1 warp per node, 128-thread blocks
    const int gemmGrid = (N_NODES + 127) / 128;

    // one-time weight splits
    k_splitW<<<(128 * IN_FEATS / 2 + 255) / 256, 256>>>(W1, w1hi, w1lo, 128 * IN_FEATS / 2);
    k_splitW<<<(128 * HIDDEN / 2 + 255) / 256, 256>>>(W2, w2hi, w2lo, 128 * HIDDEN / 2);

    // CSR by dst (rebuilt every call; graph-capture safe, no allocations)
    cudaMemsetAsync(degp, 0, N_NODES * sizeof(int));
    k_count<<<edgeGrid, 256>>>(dst);
    k_scan1<<<scanBlocks, 1024>>>();
    k_scan2<<<1, 128>>>(scanBlocks);
    k_scan3<<<nodeGrid, 256>>>();
    k_scatter<<<edgeGrid, 256>>>(src, dst);

    // ---- layer 1 ----
    k_gemm_bf16x3<<<gemmGrid, 256>>>(feats, w1hi, w1lo, al1, ar1, h, N_NODES, IN_FEATS);
    k_agg<<<warpGrid, 128>>>((const float4*)h, b1, (float4*)x2, 1);

    // ---- layer 2 ----
    k_gemm_bf16x3<<<gemmGrid, 256>>>(x2, w2hi, w2lo, al2, ar2, h, N_NODES, HIDDEN);
    k_agg<<<warpGrid, 128>>>((const float4*)h, b2, (float4*)out, 0);
}

// round 11
// speedup vs baseline: 1.4393x; 1.0598x over previous
#include <cuda_runtime.h>
#include <cuda_bf16.h>
#include <cuda_fp16.h>
#include <math.h>

#define N_NODES 100000
#define N_EDGES 1600000
#define IN_FEATS 256
#define HIDDEN 128
#define NEG_SLOPE 0.2f

// ---------------- scratch (device globals; allocation-free) ----------------
__device__ __half g_h[(size_t)N_NODES * HIDDEN];   // fc output, fp16 (gather-only)
__device__ float g_x2[(size_t)N_NODES * HIDDEN];   // elu(layer1 out) = layer2 input
__device__ float g_el[N_NODES];
__device__ float g_er[N_NODES];
__device__ int   g_deg[N_NODES];
__device__ int   g_inc[N_NODES];
__device__ int   g_bsum[128];
__device__ int   g_off[N_NODES + 1];
__device__ int   g_cur[N_NODES];
__device__ int   g_esrc[N_EDGES];
__device__ unsigned g_mx[2];   // encoded max(el), max(er)
// pre-split weights: packed bf16x2 hi/lo planes
__device__ unsigned g_w1hi[128 * IN_FEATS / 2];
__device__ unsigned g_w1lo[128 * IN_FEATS / 2];
__device__ unsigned g_w2hi[128 * HIDDEN / 2];
__device__ unsigned g_w2lo[128 * HIDDEN / 2];

// ---------------- CSR build ----------------
__global__ void k_count(const int* __restrict__ dst) {
    int i = blockIdx.x * blockDim.x + threadIdx.x;
    if (i < N_EDGES) atomicAdd(&g_deg[dst[i]], 1);
}

__global__ void k_scan1() {
    __shared__ int sm[1024];
    int i = blockIdx.x * 1024 + threadIdx.x;
    int v = (i < N_NODES) ? g_deg[i] : 0;
    sm[threadIdx.x] = v;
    __syncthreads();
    #pragma unroll
    for (int o = 1; o < 1024; o <<= 1) {
        int u = (threadIdx.x >= o) ? sm[threadIdx.x - o] : 0;
        __syncthreads();
        sm[threadIdx.x] += u;
        __syncthreads();
    }
    if (i < N_NODES) g_inc[i] = sm[threadIdx.x];
    if (threadIdx.x == 1023) g_bsum[blockIdx.x] = sm[1023];
}

__global__ void k_scan2(int nb) {
    __shared__ int sm[128];
    int t = threadIdx.x;
    int v = (t < nb) ? g_bsum[t] : 0;
    sm[t] = v;
    __syncthreads();
    #pragma unroll
    for (int o = 1; o < 128; o <<= 1) {
        int u = (t >= o) ? sm[t - o] : 0;
        __syncthreads();
        sm[t] += u;
        __syncthreads();
    }
    if (t < nb) g_bsum[t] = sm[t] - v;  // exclusive
}

__global__ void k_scan3() {
    int i = blockIdx.x * blockDim.x + threadIdx.x;
    if (i < N_NODES) {
        int off = g_inc[i] - g_deg[i] + g_bsum[i >> 10];
        g_off[i] = off;
        g_cur[i] = off;
    }
    if (i == 0) g_off[N_NODES] = N_EDGES;
}

__global__ void k_scatter(const int* __restrict__ src, const int* __restrict__ dst) {
    int i = blockIdx.x * blockDim.x + threadIdx.x;
    if (i < N_EDGES) {
        int p = atomicAdd(&g_cur[dst[i]], 1);
        g_esrc[p] = src[i];
    }
}

// ---------------- fp32 -> bf16 hi/lo helpers ----------------
__device__ __forceinline__ unsigned pack_hi(float a, float b, float& la, float& lb) {
    __nv_bfloat16 ha = __float2bfloat16_rn(a);
    __nv_bfloat16 hb = __float2bfloat16_rn(b);
    la = a - __bfloat162float(ha);
    lb = b - __bfloat162float(hb);
    return ((unsigned)__bfloat16_as_ushort(hb) << 16) | (unsigned)__bfloat16_as_ushort(ha);
}

__device__ __forceinline__ unsigned pack_lo(float la, float lb) {
    return ((unsigned)__bfloat16_as_ushort(__float2bfloat16_rn(lb)) << 16) |
           (unsigned)__bfloat16_as_ushort(__float2bfloat16_rn(la));
}

// one-time weight split: W[128,K] fp32 -> hi/lo packed bf16x2 planes
__global__ void k_splitW(const float* __restrict__ W, unsigned* __restrict__ hi,
                         unsigned* __restrict__ lo, int npairs) {
    int i = blockIdx.x * blockDim.x + threadIdx.x;
    if (i < npairs) {
        float a = W[2 * i], b = W[2 * i + 1];
        float la, lb;
        unsigned h = pack_hi(a, b, la, lb);
        hi[i] = h;
        lo[i] = pack_lo(la, lb);
    }
}

// ---------------- bf16x3 tensor-core GEMM + fused el/er, fp16 C ----------------
// H[M,128] (fp16) = A[M,K] @ W[128,K]^T ; g_el/g_er = C-row dot al/ar (fp32).
// 128x128 tile, 256 threads (8 warps, each 64x32), BK=32, register prefetch.

#define SSTR 18   // uint32 (bf16x2-pair) stride per row: 16 pairs + 2 pad

__device__ __forceinline__ void mma16816(float* d, const unsigned* a, const unsigned* b) {
    asm volatile(
        "mma.sync.aligned.m16n8k16.row.col.f32.bf16.bf16.f32 "
        "{%0,%1,%2,%3}, {%4,%5,%6,%7}, {%8,%9}, {%0,%1,%2,%3};\n"
        : "+f"(d[0]), "+f"(d[1]), "+f"(d[2]), "+f"(d[3])
        : "r"(a[0]), "r"(a[1]), "r"(a[2]), "r"(a[3]), "r"(b[0]), "r"(b[1]));
}

__global__ __launch_bounds__(256) void k_gemm_bf16x3(
    const float* __restrict__ A,
    const unsigned* __restrict__ Whi, const unsigned* __restrict__ Wlo,
    const float* __restrict__ al, const float* __restrict__ ar,
    __half* __restrict__ H, int M, int K)
{
    __shared__ unsigned sAhi[128 * SSTR];
    __shared__ unsigned sAlo[128 * SSTR];
    __shared__ unsigned sBhi[128 * SSTR];
    __shared__ unsigned sBlo[128 * SSTR];
    __shared__ float sel[128], ser[128];

    const int tid  = threadIdx.x;
    const int lane = tid & 31, wid = tid >> 5;
    const int g = lane >> 2, t = lane & 3;
    const int wm = wid >> 2, wn = wid & 3;           // 2 x 4 warp grid
    const int row0 = blockIdx.x * 128;
    const int K2 = K >> 1;                            // pairs per W row

    if (tid < 128) { sel[tid] = 0.f; ser[tid] = 0.f; }

    float acc[4][4][4];
    #pragma unroll
    for (int mt = 0; mt < 4; mt++)
        #pragma unroll
        for (int nt = 0; nt < 4; nt++)
            #pragma unroll
            for (int j = 0; j < 4; j++) acc[mt][nt][j] = 0.f;

    int lrow[4], lq[4];
    #pragma unroll
    for (int i = 0; i < 4; i++) { int idx = tid + i * 256; lrow[i] = idx >> 3; lq[i] = idx & 7; }

    float4 ra[4];
    uint2 bh[4], bl[4];
    const int NC = K / 32;

    // prologue: load chunk 0 to registers
    #pragma unroll
    for (int i = 0; i < 4; i++) {
        int gr = row0 + lrow[i];
        ra[i] = (gr < M) ? *(const float4*)(A + (size_t)gr * K + lq[i] * 4)
                         : make_float4(0.f, 0.f, 0.f, 0.f);
        int bidx = lrow[i] * K2 + lq[i] * 2;
        bh[i] = *(const uint2*)(Whi + bidx);
        bl[i] = *(const uint2*)(Wlo + bidx);
    }

    for (int c = 0; c < NC; c++) {
        // regs -> smem (A split into bf16 hi/lo; B pre-split)
        #pragma unroll
        for (int i = 0; i < 4; i++) {
            int base = lrow[i] * SSTR + lq[i] * 2;
            float l0, l1, l2, l3;
            unsigned h0 = pack_hi(ra[i].x, ra[i].y, l0, l1);
            unsigned h1 = pack_hi(ra[i].z, ra[i].w, l2, l3);
            sAhi[base] = h0; sAhi[base + 1] = h1;
            sAlo[base] = pack_lo(l0, l1); sAlo[base + 1] = pack_lo(l2, l3);
            sBhi[base] = bh[i].x; sBhi[base + 1] = bh[i].y;
            sBlo[base] = bl[i].x; sBlo[base + 1] = bl[i].y;
        }
        __syncthreads();

        // prefetch next chunk while MMAs run
        if (c + 1 < NC) {
            int k0 = (c + 1) * 32;
            #pragma unroll
            for (int i = 0; i < 4; i++) {
                int gr = row0 + lrow[i];
                ra[i] = (gr < M) ? *(const float4*)(A + (size_t)gr * K + k0 + lq[i] * 4)
                                 : make_float4(0.f, 0.f, 0.f, 0.f);
                int bidx = lrow[i] * K2 + (k0 >> 1) + lq[i] * 2;
                bh[i] = *(const uint2*)(Whi + bidx);
                bl[i] = *(const uint2*)(Wlo + bidx);
            }
        }

        #pragma unroll
        for (int ks = 0; ks < 2; ks++) {
            const int pb = ks * 8;
            unsigned fahi[4][4], falo[4][4], fbhi[4][2], fblo[4][2];
            #pragma unroll
            for (int mt = 0; mt < 4; mt++) {
                int r0 = (wm * 64 + mt * 16 + g) * SSTR + pb + t;
                int r1 = r0 + 8 * SSTR;
                fahi[mt][0] = sAhi[r0];     fahi[mt][1] = sAhi[r1];
                fahi[mt][2] = sAhi[r0 + 4]; fahi[mt][3] = sAhi[r1 + 4];
                falo[mt][0] = sAlo[r0];     falo[mt][1] = sAlo[r1];
                falo[mt][2] = sAlo[r0 + 4]; falo[mt][3] = sAlo[r1 + 4];
            }
            #pragma unroll
            for (int nt = 0; nt < 4; nt++) {
                int rn = (wn * 32 + nt * 8 + g) * SSTR + pb + t;
                fbhi[nt][0] = sBhi[rn]; fbhi[nt][1] = sBhi[rn + 4];
                fblo[nt][0] = sBlo[rn]; fblo[nt][1] = sBlo[rn + 4];
            }
            #pragma unroll
            for (int mt = 0; mt < 4; mt++)
                #pragma unroll
                for (int nt = 0; nt < 4; nt++) {
                    mma16816(acc[mt][nt], fahi[mt], fbhi[nt]);
                    mma16816(acc[mt][nt], fahi[mt], fblo[nt]);
                    mma16816(acc[mt][nt], falo[mt], fbhi[nt]);
                }
        }
        __syncthreads();
    }

    // epilogue: store H (fp16), and fused el/er row dots (fp32)
    float alv[8], arv[8];
    #pragma unroll
    for (int nt = 0; nt < 4; nt++) {
        int cix = wn * 32 + nt * 8 + t * 2;
        alv[2 * nt] = al[cix];     alv[2 * nt + 1] = al[cix + 1];
        arv[2 * nt] = ar[cix];     arv[2 * nt + 1] = ar[cix + 1];
    }

    #pragma unroll
    for (int mt = 0; mt < 4; mt++) {
        float eA = 0.f, rA = 0.f, eB = 0.f, rB = 0.f;
        #pragma unroll
        for (int nt = 0; nt < 4; nt++) {
            int r = row0 + wm * 64 + mt * 16 + g;
            int col = wn * 32 + nt * 8 + t * 2;
            if (r < M)
                *(__half2*)(H + (size_t)r * 128 + col) =
                    __floats2half2_rn(acc[mt][nt][0], acc[mt][nt][1]);
            if (r + 8 < M)
                *(__half2*)(H + (size_t)(r + 8) * 128 + col) =
                    __floats2half2_rn(acc[mt][nt][2], acc[mt][nt][3]);
            eA += acc[mt][nt][0] * alv[2 * nt] + acc[mt][nt][1] * alv[2 * nt + 1];
            rA += acc[mt][nt][0] * arv[2 * nt] + acc[mt][nt][1] * arv[2 * nt + 1];
            eB += acc[mt][nt][2] * alv[2 * nt] + acc[mt][nt][3] * alv[2 * nt + 1];
            rB += acc[mt][nt][2] * arv[2 * nt] + acc[mt][nt][3] * arv[2 * nt + 1];
        }
        #pragma unroll
        for (int o = 1; o <= 2; o <<= 1) {
            eA += __shfl_xor_sync(0xffffffffu, eA, o);
            rA += __shfl_xor_sync(0xffffffffu, rA, o);
            eB += __shfl_xor_sync(0xffffffffu, eB, o);
            rB += __shfl_xor_sync(0xffffffffu, rB, o);
        }
        if (t == 0) {
            int lr0 = wm * 64 + mt * 16 + g;
            atomicAdd(&sel[lr0], eA);     atomicAdd(&ser[lr0], rA);
            atomicAdd(&sel[lr0 + 8], eB); atomicAdd(&ser[lr0 + 8], rB);
        }
    }
    __syncthreads();
    if (tid < 128 && row0 + tid < M) {
        g_el[row0 + tid] = sel[tid];
        g_er[row0 + tid] = ser[tid];
    }
}

// ---------------- global max of el/er (for shift-invariant softmax) --------
__device__ __forceinline__ unsigned encf(float f) {
    unsigned u = __float_as_uint(f);
    return (u >> 31) ? ~u : (u | 0x80000000u);
}
__device__ __forceinline__ float decf(unsigned e) {
    return (e >> 31) ? __uint_as_float(e ^ 0x80000000u) : __uint_as_float(~e);
}

__global__ void k_maxelr() {
    int i = blockIdx.x * blockDim.x + threadIdx.x;
    float a = -1e30f, b = -1e30f;
    for (; i < N_NODES; i += gridDim.x * blockDim.x) {
        a = fmaxf(a, g_el[i]);
        b = fmaxf(b, g_er[i]);
    }
    #pragma unroll
    for (int o = 16; o; o >>= 1) {
        a = fmaxf(a, __shfl_xor_sync(0xffffffffu, a, o));
        b = fmaxf(b, __shfl_xor_sync(0xffffffffu, b, o));
    }
    if ((threadIdx.x & 31) == 0) {
        atomicMax(&g_mx[0], encf(a));
        atomicMax(&g_mx[1], encf(b));
    }
}

// ---------------- single-pass segment softmax + aggregation (fp16 gathers) ----
// one warp per dst node; lane owns 4 feature cols (8 B per gather row).
__global__ void k_agg(const __half* __restrict__ Hm,
                      const float* __restrict__ bias,
                      float4* __restrict__ out4, int do_elu)
{
    int warp = (blockIdx.x * blockDim.x + threadIdx.x) >> 5;
    int lane = threadIdx.x & 31;
    if (warp >= N_NODES) return;
    int d = warp;
    int s = g_off[d], e = g_off[d + 1];
    float4 bv = ((const float4*)bias)[lane];
    float4 v;

    if (s == e) {
        v = bv;   // segment_sum over empty set = 0, plus bias
    } else {
        // global shift m >= (segment max - small gap): softmax shift-invariant,
        // exp stays well inside range (score spread << 87).
        float me = decf(g_mx[0]) + decf(g_mx[1]);
        float m = (me > 0.f) ? me : NEG_SLOPE * me;
        float er_d = g_er[d];
        float4 acc = make_float4(0.f, 0.f, 0.f, 0.f);
        float sumw = 0.f;
        int i = s;
        for (; i + 3 < e; i += 4) {
            int sn0 = g_esrc[i],     sn1 = g_esrc[i + 1];
            int sn2 = g_esrc[i + 2], sn3 = g_esrc[i + 3];
            float2 r0 = *(const float2*)(Hm + (size_t)sn0 * 128 + lane * 4);
            float2 r1 = *(const float2*)(Hm + (size_t)sn1 * 128 + lane * 4);
            float2 r2 = *(const float2*)(Hm + (size_t)sn2 * 128 + lane * 4);
            float2 r3 = *(const float2*)(Hm + (size_t)sn3 * 128 + lane * 4);
            float x0 = g_el[sn0] + er_d, x1 = g_el[sn1] + er_d;
            float x2v = g_el[sn2] + er_d, x3 = g_el[sn3] + er_d;
            float w0 = __expf(((x0 > 0.f) ? x0 : NEG_SLOPE * x0) - m);
            float w1 = __expf(((x1 > 0.f) ? x1 : NEG_SLOPE * x1) - m);
            float w2 = __expf(((x2v > 0.f) ? x2v : NEG_SLOPE * x2v) - m);
            float w3 = __expf(((x3 > 0.f) ? x3 : NEG_SLOPE * x3) - m);
            sumw += (w0 + w1) + (w2 + w3);
            float2 a0 = __half22float2(*(__half2*)&r0.x), b0 = __half22float2(*(__half2*)&r0.y);
            float2 a1 = __half22float2(*(__half2*)&r1.x), b1 = __half22float2(*(__half2*)&r1.y);
            float2 a2 = __half22float2(*(__half2*)&r2.x), b2 = __half22float2(*(__half2*)&r2.y);
            float2 a3 = __half22float2(*(__half2*)&r3.x), b3 = __half22float2(*(__half2*)&r3.y);
            acc.x += w0 * a0.x + w1 * a1.x + w2 * a2.x + w3 * a3.x;
            acc.y += w0 * a0.y + w1 * a1.y + w2 * a2.y + w3 * a3.y;
            acc.z += w0 * b0.x + w1 * b1.x + w2 * b2.x + w3 * b3.x;
            acc.w += w0 * b0.y + w1 * b1.y + w2 * b2.y + w3 * b3.y;
        }
        for (; i < e; i++) {
            int sn = g_esrc[i];
            float2 r0 = *(const float2*)(Hm + (size_t)sn * 128 + lane * 4);
            float x = g_el[sn] + er_d;
            float w = __expf(((x > 0.f) ? x : NEG_SLOPE * x) - m);
            sumw += w;
            float2 a0 = __half22float2(*(__half2*)&r0.x), b0 = __half22float2(*(__half2*)&r0.y);
            acc.x += w * a0.x; acc.y += w * a0.y;
            acc.z += w * b0.x; acc.w += w * b0.y;
        }
        float inv = 1.f / sumw;
        v = make_float4(acc.x * inv + bv.x, acc.y * inv + bv.y,
                        acc.z * inv + bv.z, acc.w * inv + bv.w);
    }

    if (do_elu) {
        v.x = (v.x > 0.f) ? v.x : (__expf(v.x) - 1.f);
        v.y = (v.y > 0.f) ? v.y : (__expf(v.y) - 1.f);
        v.z = (v.z > 0.f) ? v.z : (__expf(v.z) - 1.f);
        v.w = (v.w > 0.f) ? v.w : (__expf(v.w) - 1.f);
    }
    out4[(size_t)d * 32 + lane] = v;
}

// ---------------- launch ----------------
extern "C" void kernel_launch(void* const* d_in, const int* in_sizes, int n_in,
                              void* d_out, int out_size)
{
    const float* feats = (const float*)d_in[0];
    const int*   src   = (const int*)d_in[1];
    const int*   dst   = (const int*)d_in[2];
    const float* W1    = (const float*)d_in[3];
    const float* al1   = (const float*)d_in[4];
    const float* ar1   = (const float*)d_in[5];
    const float* b1    = (const float*)d_in[6];
    const float* W2    = (const float*)d_in[7];
    const float* al2   = (const float*)d_in[8];
    const float* ar2   = (const float*)d_in[9];
    const float* b2    = (const float*)d_in[10];
    float* out = (float*)d_out;

    __half* h;
    float* x2;
    unsigned *w1hi, *w1lo, *w2hi, *w2lo, *mxp;
    int *degp;
    cudaGetSymbolAddress((void**)&h, g_h);
    cudaGetSymbolAddress((void**)&x2, g_x2);
    cudaGetSymbolAddress((void**)&w1hi, g_w1hi);
    cudaGetSymbolAddress((void**)&w1lo, g_w1lo);
    cudaGetSymbolAddress((void**)&w2hi, g_w2hi);
    cudaGetSymbolAddress((void**)&w2lo, g_w2lo);
    cudaGetSymbolAddress((void**)&degp, g_deg);
    cudaGetSymbolAddress((void**)&mxp, g_mx);

    const int nodeGrid = (N_NODES + 255) / 256;
    const int edgeGrid = (N_EDGES + 255) / 256;
    const int scanBlocks = (N_NODES + 1023) / 1024;
    const int warpGrid = (N_NODES * 32 + 127) / 128;   // 1 warp per node, 128-thread blocks
    const int gemmGrid = (N_NODES + 127) / 128;

    // one-time weight splits
    k_splitW<<<(128 * IN_FEATS / 2 + 255) / 256, 256>>>(W1, w1hi, w1lo, 128 * IN_FEATS / 2);
    k_splitW<<<(128 * HIDDEN / 2 + 255) / 256, 256>>>(W2, w2hi, w2lo, 128 * HIDDEN / 2);

    // CSR by dst (rebuilt every call; graph-capture safe, no allocations)
    cudaMemsetAsync(degp, 0, N_NODES * sizeof(int));
    k_count<<<edgeGrid, 256>>>(dst);
    k_scan1<<<scanBlocks, 1024>>>();
    k_scan2<<<1, 128>>>(scanBlocks);
    k_scan3<<<nodeGrid, 256>>>();
    k_scatter<<<edgeGrid, 256>>>(src, dst);

    // ---- layer 1 ----
    k_gemm_bf16x3<<<gemmGrid, 256>>>(feats, w1hi, w1lo, al1, ar1, h, N_NODES, IN_FEATS);
    cudaMemsetAsync(mxp, 0, 2 * sizeof(unsigned));
    k_maxelr<<<96, 256>>>();
    k_agg<<<warpGrid, 128>>>(h, b1, (float4*)x2, 1);

    // ---- layer 2 ----
    k_gemm_bf16x3<<<gemmGrid, 256>>>(x2, w2hi, w2lo, al2, ar2, h, N_NODES, HIDDEN);
    cudaMemsetAsync(mxp, 0, 2 * sizeof(unsigned));
    k_maxelr<<<96, 256>>>();
    k_agg<<<warpGrid, 128>>>(h, b2, (float4*)out, 0);
}

// round 12
// speedup vs baseline: 1.6138x; 1.1212x over previous
#include <cuda_runtime.h>
#include <cuda_bf16.h>
#include <cuda_fp16.h>
#include <math.h>

#define N_NODES 100000
#define N_EDGES 1600000
#define IN_FEATS 256
#define HIDDEN 128
#define NEG_SLOPE 0.2f

// ---------------- scratch (device globals; allocation-free) ----------------
__device__ __half g_h[(size_t)N_NODES * HIDDEN];   // fc output, fp16 (gather-only)
__device__ float g_x2[(size_t)N_NODES * HIDDEN];   // elu(layer1 out) = layer2 input
__device__ float g_el[N_NODES];
__device__ float g_er[N_NODES];
__device__ int   g_deg[N_NODES];
__device__ int   g_inc[N_NODES];
__device__ int   g_bsum[128];
__device__ int   g_off[N_NODES + 1];
__device__ int   g_cur[N_NODES];
__device__ int   g_esrc[N_EDGES];
__device__ unsigned g_mx[4];   // encoded max(el), max(er) per layer
// pre-split weights: packed bf16x2 hi/lo planes
__device__ unsigned g_w1hi[128 * IN_FEATS / 2];
__device__ unsigned g_w1lo[128 * IN_FEATS / 2];
__device__ unsigned g_w2hi[128 * HIDDEN / 2];
__device__ unsigned g_w2lo[128 * HIDDEN / 2];

// ---------------- CSR build ----------------
__global__ void k_count(const int* __restrict__ dst) {
    int i = blockIdx.x * blockDim.x + threadIdx.x;
    if (i < N_EDGES) atomicAdd(&g_deg[dst[i]], 1);
}

__global__ void k_scan1() {
    __shared__ int sm[1024];
    int i = blockIdx.x * 1024 + threadIdx.x;
    int v = (i < N_NODES) ? g_deg[i] : 0;
    sm[threadIdx.x] = v;
    __syncthreads();
    #pragma unroll
    for (int o = 1; o < 1024; o <<= 1) {
        int u = (threadIdx.x >= o) ? sm[threadIdx.x - o] : 0;
        __syncthreads();
        sm[threadIdx.x] += u;
        __syncthreads();
    }
    if (i < N_NODES) g_inc[i] = sm[threadIdx.x];
    if (threadIdx.x == 1023) g_bsum[blockIdx.x] = sm[1023];
}

__global__ void k_scan2(int nb) {
    __shared__ int sm[128];
    int t = threadIdx.x;
    int v = (t < nb) ? g_bsum[t] : 0;
    sm[t] = v;
    __syncthreads();
    #pragma unroll
    for (int o = 1; o < 128; o <<= 1) {
        int u = (t >= o) ? sm[t - o] : 0;
        __syncthreads();
        sm[t] += u;
        __syncthreads();
    }
    if (t < nb) g_bsum[t] = sm[t] - v;  // exclusive
}

__global__ void k_scan3() {
    int i = blockIdx.x * blockDim.x + threadIdx.x;
    if (i < N_NODES) {
        int off = g_inc[i] - g_deg[i] + g_bsum[i >> 10];
        g_off[i] = off;
        g_cur[i] = off;
    }
    if (i == 0) g_off[N_NODES] = N_EDGES;
}

__global__ void k_scatter(const int* __restrict__ src, const int* __restrict__ dst) {
    int i = blockIdx.x * blockDim.x + threadIdx.x;
    if (i < N_EDGES) {
        int p = atomicAdd(&g_cur[dst[i]], 1);
        g_esrc[p] = src[i];
    }
}

// ---------------- fp32 -> bf16 hi/lo helpers ----------------
__device__ __forceinline__ unsigned pack_hi(float a, float b, float& la, float& lb) {
    __nv_bfloat16 ha = __float2bfloat16_rn(a);
    __nv_bfloat16 hb = __float2bfloat16_rn(b);
    la = a - __bfloat162float(ha);
    lb = b - __bfloat162float(hb);
    return ((unsigned)__bfloat16_as_ushort(hb) << 16) | (unsigned)__bfloat16_as_ushort(ha);
}

__device__ __forceinline__ unsigned pack_lo(float la, float lb) {
    return ((unsigned)__bfloat16_as_ushort(__float2bfloat16_rn(lb)) << 16) |
           (unsigned)__bfloat16_as_ushort(__float2bfloat16_rn(la));
}

__global__ void k_splitW(const float* __restrict__ W, unsigned* __restrict__ hi,
                         unsigned* __restrict__ lo, int npairs) {
    int i = blockIdx.x * blockDim.x + threadIdx.x;
    if (i < npairs) {
        float a = W[2 * i], b = W[2 * i + 1];
        float la, lb;
        unsigned h = pack_hi(a, b, la, lb);
        hi[i] = h;
        lo[i] = pack_lo(la, lb);
    }
}

// ---------------- float<->ordered-unsigned for atomicMax ----------------
__device__ __forceinline__ unsigned encf(float f) {
    unsigned u = __float_as_uint(f);
    return (u >> 31) ? ~u : (u | 0x80000000u);
}
__device__ __forceinline__ float decf(unsigned e) {
    return (e >> 31) ? __uint_as_float(e ^ 0x80000000u) : __uint_as_float(~e);
}

// ---------------- bf16x3 tensor-core GEMM + fused el/er + global max ------
// H[M,128] (fp16) = A[M,K] @ W[128,K]^T ; g_el/g_er = C-row dot al/ar (fp32);
// per-layer global max of el/er accumulated via atomicMax into g_mx.
// 128x128 tile, 256 threads (8 warps, each 64x32), BK=32, register prefetch,
// DOUBLE-BUFFERED chunk SMEM with a single __syncthreads per chunk.

#define SSTR 18          // uint32 pairs per row: 16 + 2 pad
#define BUFW (4 * 128 * SSTR)   // words per buffer (Ahi,Alo,Bhi,Blo)

__device__ __forceinline__ void mma16816(float* d, const unsigned* a, const unsigned* b) {
    asm volatile(
        "mma.sync.aligned.m16n8k16.row.col.f32.bf16.bf16.f32 "
        "{%0,%1,%2,%3}, {%4,%5,%6,%7}, {%8,%9}, {%0,%1,%2,%3};\n"
        : "+f"(d[0]), "+f"(d[1]), "+f"(d[2]), "+f"(d[3])
        : "r"(a[0]), "r"(a[1]), "r"(a[2]), "r"(a[3]), "r"(b[0]), "r"(b[1]));
}

__global__ __launch_bounds__(256) void k_gemm_bf16x3(
    const float* __restrict__ A,
    const unsigned* __restrict__ Whi, const unsigned* __restrict__ Wlo,
    const float* __restrict__ al, const float* __restrict__ ar,
    __half* __restrict__ H, int M, int K, int layer)
{
    extern __shared__ unsigned dyn[];
    float* sel = (float*)(dyn + 2 * BUFW);
    float* ser = sel + 128;
    float* smax = ser + 128;     // 8 floats: warp maxima

    const int tid  = threadIdx.x;
    const int lane = tid & 31, wid = tid >> 5;
    const int g = lane >> 2, t = lane & 3;
    const int wm = wid >> 2, wn = wid & 3;           // 2 x 4 warp grid
    const int row0 = blockIdx.x * 128;
    const int K2 = K >> 1;                            // pairs per W row

    if (tid < 128) { sel[tid] = 0.f; ser[tid] = 0.f; }

    float acc[4][4][4];
    #pragma unroll
    for (int mt = 0; mt < 4; mt++)
        #pragma unroll
        for (int nt = 0; nt < 4; nt++)
            #pragma unroll
            for (int j = 0; j < 4; j++) acc[mt][nt][j] = 0.f;

    int lrow[4], lq[4];
    #pragma unroll
    for (int i = 0; i < 4; i++) { int idx = tid + i * 256; lrow[i] = idx >> 3; lq[i] = idx & 7; }

    float4 ra[4];
    uint2 bh[4], bl[4];
    const int NC = K / 32;

    // prologue: load chunk 0 to registers
    #pragma unroll
    for (int i = 0; i < 4; i++) {
        int gr = row0 + lrow[i];
        ra[i] = (gr < M) ? *(const float4*)(A + (size_t)gr * K + lq[i] * 4)
                         : make_float4(0.f, 0.f, 0.f, 0.f);
        int bidx = lrow[i] * K2 + lq[i] * 2;
        bh[i] = *(const uint2*)(Whi + bidx);
        bl[i] = *(const uint2*)(Wlo + bidx);
    }

    for (int c = 0; c < NC; c++) {
        unsigned* sAhi = dyn + (c & 1) * BUFW;
        unsigned* sAlo = sAhi + 128 * SSTR;
        unsigned* sBhi = sAlo + 128 * SSTR;
        unsigned* sBlo = sBhi + 128 * SSTR;

        // regs -> smem (A split into bf16 hi/lo; B pre-split)
        #pragma unroll
        for (int i = 0; i < 4; i++) {
            int base = lrow[i] * SSTR + lq[i] * 2;
            float l0, l1, l2, l3;
            unsigned h0 = pack_hi(ra[i].x, ra[i].y, l0, l1);
            unsigned h1 = pack_hi(ra[i].z, ra[i].w, l2, l3);
            sAhi[base] = h0; sAhi[base + 1] = h1;
            sAlo[base] = pack_lo(l0, l1); sAlo[base + 1] = pack_lo(l2, l3);
            sBhi[base] = bh[i].x; sBhi[base + 1] = bh[i].y;
            sBlo[base] = bl[i].x; sBlo[base + 1] = bl[i].y;
        }
        __syncthreads();   // single barrier per chunk (double-buffered)

        // prefetch next chunk while MMAs run
        if (c + 1 < NC) {
            int k0 = (c + 1) * 32;
            #pragma unroll
            for (int i = 0; i < 4; i++) {
                int gr = row0 + lrow[i];
                ra[i] = (gr < M) ? *(const float4*)(A + (size_t)gr * K + k0 + lq[i] * 4)
                                 : make_float4(0.f, 0.f, 0.f, 0.f);
                int bidx = lrow[i] * K2 + (k0 >> 1) + lq[i] * 2;
                bh[i] = *(const uint2*)(Whi + bidx);
                bl[i] = *(const uint2*)(Wlo + bidx);
            }
        }

        #pragma unroll
        for (int ks = 0; ks < 2; ks++) {
            const int pb = ks * 8;
            unsigned fahi[4][4], falo[4][4], fbhi[4][2], fblo[4][2];
            #pragma unroll
            for (int mt = 0; mt < 4; mt++) {
                int r0 = (wm * 64 + mt * 16 + g) * SSTR + pb + t;
                int r1 = r0 + 8 * SSTR;
                fahi[mt][0] = sAhi[r0];     fahi[mt][1] = sAhi[r1];
                fahi[mt][2] = sAhi[r0 + 4]; fahi[mt][3] = sAhi[r1 + 4];
                falo[mt][0] = sAlo[r0];     falo[mt][1] = sAlo[r1];
                falo[mt][2] = sAlo[r0 + 4]; falo[mt][3] = sAlo[r1 + 4];
            }
            #pragma unroll
            for (int nt = 0; nt < 4; nt++) {
                int rn = (wn * 32 + nt * 8 + g) * SSTR + pb + t;
                fbhi[nt][0] = sBhi[rn]; fbhi[nt][1] = sBhi[rn + 4];
                fblo[nt][0] = sBlo[rn]; fblo[nt][1] = sBlo[rn + 4];
            }
            #pragma unroll
            for (int mt = 0; mt < 4; mt++)
                #pragma unroll
                for (int nt = 0; nt < 4; nt++) {
                    mma16816(acc[mt][nt], fahi[mt], fbhi[nt]);
                    mma16816(acc[mt][nt], fahi[mt], fblo[nt]);
                    mma16816(acc[mt][nt], falo[mt], fbhi[nt]);
                }
        }
    }
    __syncthreads();

    // epilogue: store H (fp16), and fused el/er row dots (fp32)
    float alv[8], arv[8];
    #pragma unroll
    for (int nt = 0; nt < 4; nt++) {
        int cix = wn * 32 + nt * 8 + t * 2;
        alv[2 * nt] = al[cix];     alv[2 * nt + 1] = al[cix + 1];
        arv[2 * nt] = ar[cix];     arv[2 * nt + 1] = ar[cix + 1];
    }

    #pragma unroll
    for (int mt = 0; mt < 4; mt++) {
        float eA = 0.f, rA = 0.f, eB = 0.f, rB = 0.f;
        #pragma unroll
        for (int nt = 0; nt < 4; nt++) {
            int r = row0 + wm * 64 + mt * 16 + g;
            int col = wn * 32 + nt * 8 + t * 2;
            if (r < M)
                *(__half2*)(H + (size_t)r * 128 + col) =
                    __floats2half2_rn(acc[mt][nt][0], acc[mt][nt][1]);
            if (r + 8 < M)
                *(__half2*)(H + (size_t)(r + 8) * 128 + col) =
                    __floats2half2_rn(acc[mt][nt][2], acc[mt][nt][3]);
            eA += acc[mt][nt][0] * alv[2 * nt] + acc[mt][nt][1] * alv[2 * nt + 1];
            rA += acc[mt][nt][0] * arv[2 * nt] + acc[mt][nt][1] * arv[2 * nt + 1];
            eB += acc[mt][nt][2] * alv[2 * nt] + acc[mt][nt][3] * alv[2 * nt + 1];
            rB += acc[mt][nt][2] * arv[2 * nt] + acc[mt][nt][3] * arv[2 * nt + 1];
        }
        #pragma unroll
        for (int o = 1; o <= 2; o <<= 1) {
            eA += __shfl_xor_sync(0xffffffffu, eA, o);
            rA += __shfl_xor_sync(0xffffffffu, rA, o);
            eB += __shfl_xor_sync(0xffffffffu, eB, o);
            rB += __shfl_xor_sync(0xffffffffu, rB, o);
        }
        if (t == 0) {
            int lr0 = wm * 64 + mt * 16 + g;
            atomicAdd(&sel[lr0], eA);     atomicAdd(&ser[lr0], rA);
            atomicAdd(&sel[lr0 + 8], eB); atomicAdd(&ser[lr0 + 8], rB);
        }
    }
    __syncthreads();

    // write el/er and fold block max of el/er into g_mx[2*layer..]
    float mel = -3e38f, mer = -3e38f;
    if (tid < 128) {
        bool valid = (row0 + tid) < M;
        float el = sel[tid], er = ser[tid];
        if (valid) {
            g_el[row0 + tid] = el;
            g_er[row0 + tid] = er;
            mel = el; mer = er;
        }
        #pragma unroll
        for (int o = 16; o; o >>= 1) {
            mel = fmaxf(mel, __shfl_xor_sync(0xffffffffu, mel, o));
            mer = fmaxf(mer, __shfl_xor_sync(0xffffffffu, mer, o));
        }
        if (lane == 0) { smax[wid] = mel; smax[4 + wid] = mer; }
    }
    __syncthreads();
    if (tid == 0) {
        float a = fmaxf(fmaxf(smax[0], smax[1]), fmaxf(smax[2], smax[3]));
        float b = fmaxf(fmaxf(smax[4], smax[5]), fmaxf(smax[6], smax[7]));
        atomicMax(&g_mx[2 * layer], encf(a));
        atomicMax(&g_mx[2 * layer + 1], encf(b));
    }
}

// ---------------- single-pass segment softmax + aggregation (fp16 gathers) ----
__global__ void k_agg(const __half* __restrict__ Hm,
                      const float* __restrict__ bias,
                      float4* __restrict__ out4, int do_elu, int layer)
{
    int warp = (blockIdx.x * blockDim.x + threadIdx.x) >> 5;
    int lane = threadIdx.x & 31;
    if (warp >= N_NODES) return;
    int d = warp;
    int s = g_off[d], e = g_off[d + 1];
    float4 bv = ((const float4*)bias)[lane];
    float4 v;

    if (s == e) {
        v = bv;
    } else {
        float me = decf(g_mx[2 * layer]) + decf(g_mx[2 * layer + 1]);
        float m = (me > 0.f) ? me : NEG_SLOPE * me;
        float er_d = g_er[d];
        float4 acc = make_float4(0.f, 0.f, 0.f, 0.f);
        float sumw = 0.f;
        int i = s;
        for (; i + 3 < e; i += 4) {
            int sn0 = g_esrc[i],     sn1 = g_esrc[i + 1];
            int sn2 = g_esrc[i + 2], sn3 = g_esrc[i + 3];
            float2 r0 = *(const float2*)(Hm + (size_t)sn0 * 128 + lane * 4);
            float2 r1 = *(const float2*)(Hm + (size_t)sn1 * 128 + lane * 4);
            float2 r2 = *(const float2*)(Hm + (size_t)sn2 * 128 + lane * 4);
            float2 r3 = *(const float2*)(Hm + (size_t)sn3 * 128 + lane * 4);
            float x0 = g_el[sn0] + er_d, x1 = g_el[sn1] + er_d;
            float x2v = g_el[sn2] + er_d, x3 = g_el[sn3] + er_d;
            float w0 = __expf(((x0 > 0.f) ? x0 : NEG_SLOPE * x0) - m);
            float w1 = __expf(((x1 > 0.f) ? x1 : NEG_SLOPE * x1) - m);
            float w2 = __expf(((x2v > 0.f) ? x2v : NEG_SLOPE * x2v) - m);
            float w3 = __expf(((x3 > 0.f) ? x3 : NEG_SLOPE * x3) - m);
            sumw += (w0 + w1) + (w2 + w3);
            float2 a0 = __half22float2(*(__half2*)&r0.x), b0 = __half22float2(*(__half2*)&r0.y);
            float2 a1 = __half22float2(*(__half2*)&r1.x), b1 = __half22float2(*(__half2*)&r1.y);
            float2 a2 = __half22float2(*(__half2*)&r2.x), b2 = __half22float2(*(__half2*)&r2.y);
            float2 a3 = __half22float2(*(__half2*)&r3.x), b3 = __half22float2(*(__half2*)&r3.y);
            acc.x += w0 * a0.x + w1 * a1.x + w2 * a2.x + w3 * a3.x;
            acc.y += w0 * a0.y + w1 * a1.y + w2 * a2.y + w3 * a3.y;
            acc.z += w0 * b0.x + w1 * b1.x + w2 * b2.x + w3 * b3.x;
            acc.w += w0 * b0.y + w1 * b1.y + w2 * b2.y + w3 * b3.y;
        }
        for (; i < e; i++) {
            int sn = g_esrc[i];
            float2 r0 = *(const float2*)(Hm + (size_t)sn * 128 + lane * 4);
            float x = g_el[sn] + er_d;
            float w = __expf(((x > 0.f) ? x : NEG_SLOPE * x) - m);
            sumw += w;
            float2 a0 = __half22float2(*(__half2*)&r0.x), b0 = __half22float2(*(__half2*)&r0.y);
            acc.x += w * a0.x; acc.y += w * a0.y;
            acc.z += w * b0.x; acc.w += w * b0.y;
        }
        float inv = 1.f / sumw;
        v = make_float4(acc.x * inv + bv.x, acc.y * inv + bv.y,
                        acc.z * inv + bv.z, acc.w * inv + bv.w);
    }

    if (do_elu) {
        v.x = (v.x > 0.f) ? v.x : (__expf(v.x) - 1.f);
        v.y = (v.y > 0.f) ? v.y : (__expf(v.y) - 1.f);
        v.z = (v.z > 0.f) ? v.z : (__expf(v.z) - 1.f);
        v.w = (v.w > 0.f) ? v.w : (__expf(v.w) - 1.f);
    }
    out4[(size_t)d * 32 + lane] = v;
}

// ---------------- launch ----------------
extern "C" void kernel_launch(void* const* d_in, const int* in_sizes, int n_in,
                              void* d_out, int out_size)
{
    const float* feats = (const float*)d_in[0];
    const int*   src   = (const int*)d_in[1];
    const int*   dst   = (const int*)d_in[2];
    const float* W1    = (const float*)d_in[3];
    const float* al1   = (const float*)d_in[4];
    const float* ar1   = (const float*)d_in[5];
    const float* b1    = (const float*)d_in[6];
    const float* W2    = (const float*)d_in[7];
    const float* al2   = (const float*)d_in[8];
    const float* ar2   = (const float*)d_in[9];
    const float* b2    = (const float*)d_in[10];
    float* out = (float*)d_out;

    __half* h;
    float* x2;
    unsigned *w1hi, *w1lo, *w2hi, *w2lo, *mxp;
    int *degp;
    cudaGetSymbolAddress((void**)&h, g_h);
    cudaGetSymbolAddress((void**)&x2, g_x2);
    cudaGetSymbolAddress((void**)&w1hi, g_w1hi);
    cudaGetSymbolAddress((void**)&w1lo, g_w1lo);
    cudaGetSymbolAddress((void**)&w2hi, g_w2hi);
    cudaGetSymbolAddress((void**)&w2lo, g_w2lo);
    cudaGetSymbolAddress((void**)&degp, g_deg);
    cudaGetSymbolAddress((void**)&mxp, g_mx);

    // side stream + events for CSR overlap (created once; no device allocs)
    static cudaStream_t s2 = nullptr;
    static cudaEvent_t eFork = nullptr, eCsr = nullptr;
    if (s2 == nullptr) {
        cudaStreamCreateWithFlags(&s2, cudaStreamNonBlocking);
        cudaEventCreateWithFlags(&eFork, cudaEventDisableTiming);
        cudaEventCreateWithFlags(&eCsr, cudaEventDisableTiming);
    }

    const int nodeGrid = (N_NODES + 255) / 256;
    const int edgeGrid = (N_EDGES + 255) / 256;
    const int scanBlocks = (N_NODES + 1023) / 1024;
    const int warpGrid = (N_NODES * 32 + 127) / 128;
    const int gemmGrid = (N_NODES + 127) / 128;
    const int smemGemm = (2 * BUFW + 256 + 8) * 4;   // ~74.8 KB

    cudaFuncSetAttribute(k_gemm_bf16x3,
                         cudaFuncAttributeMaxDynamicSharedMemorySize, smemGemm);

    // ---- fork: CSR build on s2, concurrent with splitW + GEMM1 ----
    cudaEventRecord(eFork, 0);
    cudaStreamWaitEvent(s2, eFork, 0);
    cudaMemsetAsync(degp, 0, N_NODES * sizeof(int), s2);
    k_count<<<edgeGrid, 256, 0, s2>>>(dst);
    k_scan1<<<scanBlocks, 1024, 0, s2>>>();
    k_scan2<<<1, 128, 0, s2>>>(scanBlocks);
    k_scan3<<<nodeGrid, 256, 0, s2>>>();
    k_scatter<<<edgeGrid, 256, 0, s2>>>(src, dst);
    cudaEventRecord(eCsr, s2);

    // ---- main stream: weights + layer 1 GEMM ----
    cudaMemsetAsync(mxp, 0, 4 * sizeof(unsigned));
    k_splitW<<<(128 * IN_FEATS / 2 + 255) / 256, 256>>>(W1, w1hi, w1lo, 128 * IN_FEATS / 2);
    k_splitW<<<(128 * HIDDEN / 2 + 255) / 256, 256>>>(W2, w2hi, w2lo, 128 * HIDDEN / 2);
    k_gemm_bf16x3<<<gemmGrid, 256, smemGemm>>>(feats, w1hi, w1lo, al1, ar1, h,
                                               N_NODES, IN_FEATS, 0);
    cudaStreamWaitEvent(0, eCsr, 0);   // join CSR before aggregation
    k_agg<<<warpGrid, 128>>>(h, b1, (float4*)x2, 1, 0);

    // ---- layer 2 ----
    k_gemm_bf16x3<<<gemmGrid, 256, smemGemm>>>(x2, w2hi, w2lo, al2, ar2, h,
                                               N_NODES, HIDDEN, 1);
    k_agg<<<warpGrid, 128>>>(h, b2, (float4*)out, 0, 1);
}